// round 1
// baseline (speedup 1.0000x reference)
#include <cuda_runtime.h>
#include <cstdint>

// Problem constants
#define BB   32
#define CCH  256
#define HH   64
#define WW   64
#define HWS  (HH * WW)            // 4096
#define NROWS (BB * HWS)          // 131072
#define EDIM 256
#define NE   1024
#define CHW  (CCH * HWS)          // 1048576
#define ZQ_ELEMS (BB * CHW)       // 8388608

// Output layout (flattened tuple order):
//   [0, ZQ_ELEMS)          z_q_out (B,C,H,W) f32
//   [ZQ_ELEMS]             codebook_loss
//   [ZQ_ELEMS+1]           cls_loss (0)
//   [ZQ_ELEMS+2, +NROWS)   indices as f32

// Scratch (static device globals; no allocation allowed)
__device__ float g_zt[NROWS * EDIM];     // z transposed to (N, 256)
__device__ float g_cbnorm[NE];           // ||e||^2
__device__ int   g_idx[NROWS];           // argmin indices
__device__ float g_partials[32768];      // per-block loss partials

// ---------------------------------------------------------------------------
// Kernel 1: codebook row norms. One block per code.
// ---------------------------------------------------------------------------
__global__ void __launch_bounds__(256) cbnorm_kernel(const float* __restrict__ cb) {
    int j = blockIdx.x;
    int t = threadIdx.x;
    float v = cb[j * EDIM + t];
    float s = v * v;
    #pragma unroll
    for (int off = 16; off; off >>= 1) s += __shfl_xor_sync(0xffffffffu, s, off);
    __shared__ float ws[8];
    if ((t & 31) == 0) ws[t >> 5] = s;
    __syncthreads();
    if (t == 0) {
        float tot = 0.f;
        #pragma unroll
        for (int i = 0; i < 8; ++i) tot += ws[i];
        g_cbnorm[j] = tot;
    }
}

// ---------------------------------------------------------------------------
// Kernel 2: transpose z (B,C,HW) -> zt (B*HW, 256)
// grid (HW/32, C/32, B), block (32, 8)
// ---------------------------------------------------------------------------
__global__ void __launch_bounds__(256) transpose_kernel(const float* __restrict__ z) {
    __shared__ float t[32][33];
    int tx = threadIdx.x, ty = threadIdx.y;
    int b = blockIdx.z;
    int c0 = blockIdx.y * 32;
    int hw0 = blockIdx.x * 32;
    #pragma unroll
    for (int cc = ty; cc < 32; cc += 8)
        t[cc][tx] = z[b * CHW + (c0 + cc) * HWS + hw0 + tx];
    __syncthreads();
    #pragma unroll
    for (int rr = ty; rr < 32; rr += 8)
        g_zt[(b * HWS + hw0 + rr) * EDIM + c0 + tx] = t[tx][rr];
}

// ---------------------------------------------------------------------------
// Kernel 3: distance GEMM + fused argmin.
// 64 rows/block vs all 1024 codes. 256 threads as 16x16, 4x4 micro-tile.
// score(j) = ||e_j||^2 - 2 * dot(z_n, e_j)   (row norm constant, dropped)
// ---------------------------------------------------------------------------
#define KC 16
#define SPAD 68   // 64 + 4: keeps float4 alignment, near-conflict-free

__global__ void __launch_bounds__(256) argmin_kernel(const float* __restrict__ cb,
                                                     float* __restrict__ out_idx_f) {
    __shared__ float As[KC][SPAD];   // As[k][row]
    __shared__ float Bs[KC][SPAD];   // Bs[k][code]
    __shared__ float cbn[NE];
    __shared__ unsigned long long best[64];

    int tid = threadIdx.x;
    int tx = tid & 15;        // code group (4 codes)
    int ty = tid >> 4;        // row group (4 rows)
    int n0 = blockIdx.x * 64;

    for (int i = tid; i < NE; i += 256) cbn[i] = g_cbnorm[i];
    if (tid < 64) best[tid] = 0xFFFFFFFFFFFFFFFFULL;
    __syncthreads();

    // loader indices: each thread loads one float4 of A and one of B per chunk
    int lr = tid >> 2;          // 0..63 (row / code)
    int lq = (tid & 3) * 4;     // k offset within chunk

    for (int jt = 0; jt < 16; ++jt) {
        int j0 = jt * 64;
        float acc[4][4] = {};

        for (int kt = 0; kt < EDIM / KC; ++kt) {
            int k0 = kt * KC;
            float4 va = *(const float4*)&g_zt[(n0 + lr) * EDIM + k0 + lq];
            float4 vb = *(const float4*)&cb[(j0 + lr) * EDIM + k0 + lq];
            As[lq + 0][lr] = va.x; As[lq + 1][lr] = va.y;
            As[lq + 2][lr] = va.z; As[lq + 3][lr] = va.w;
            Bs[lq + 0][lr] = vb.x; Bs[lq + 1][lr] = vb.y;
            Bs[lq + 2][lr] = vb.z; Bs[lq + 3][lr] = vb.w;
            __syncthreads();
            #pragma unroll
            for (int k = 0; k < KC; ++k) {
                float4 a = *(const float4*)&As[k][ty * 4];
                float4 b = *(const float4*)&Bs[k][tx * 4];
                acc[0][0] += a.x * b.x; acc[0][1] += a.x * b.y;
                acc[0][2] += a.x * b.z; acc[0][3] += a.x * b.w;
                acc[1][0] += a.y * b.x; acc[1][1] += a.y * b.y;
                acc[1][2] += a.y * b.z; acc[1][3] += a.y * b.w;
                acc[2][0] += a.z * b.x; acc[2][1] += a.z * b.y;
                acc[2][2] += a.z * b.z; acc[2][3] += a.z * b.w;
                acc[3][0] += a.w * b.x; acc[3][1] += a.w * b.y;
                acc[3][2] += a.w * b.z; acc[3][3] += a.w * b.w;
            }
            __syncthreads();
        }

        // fused argmin over this 64-code tile
        #pragma unroll
        for (int i = 0; i < 4; ++i) {
            float bsc = __int_as_float(0x7f800000);  // +inf
            int bj = 0;
            #pragma unroll
            for (int j = 0; j < 4; ++j) {
                int jj = j0 + tx * 4 + j;
                float s = cbn[jj] - 2.0f * acc[i][j];
                if (s < bsc) { bsc = s; bj = jj; }
            }
            // order-preserving float->uint map, pack with index
            unsigned ub = __float_as_uint(bsc);
            ub = (ub & 0x80000000u) ? ~ub : (ub | 0x80000000u);
            unsigned long long pk = ((unsigned long long)ub << 32) | (unsigned)bj;
            #pragma unroll
            for (int off = 8; off; off >>= 1) {
                unsigned long long o = __shfl_xor_sync(0xffffffffu, pk, off, 16);
                pk = (o < pk) ? o : pk;
            }
            if (tx == 0) {
                unsigned long long cur = best[ty * 4 + i];
                best[ty * 4 + i] = (pk < cur) ? pk : cur;   // same thread per row, no race
            }
        }
    }
    __syncthreads();

    for (int r = tid; r < 64; r += 256) {
        int bi = (int)(best[r] & 0xffffffffULL);
        g_idx[n0 + r] = bi;
        out_idx_f[n0 + r] = (float)bi;
    }
}

// ---------------------------------------------------------------------------
// Kernel 4: gather z_q = codebook[idx], write transposed to (B,C,H,W),
// accumulate squared error. grid (HW/32, C/32, B), block (32, 8)
// ---------------------------------------------------------------------------
__global__ void __launch_bounds__(256) gather_kernel(const float* __restrict__ z,
                                                     const float* __restrict__ cb,
                                                     float* __restrict__ zq_out) {
    __shared__ float tile[32][33];
    __shared__ int sidx[32];
    __shared__ float ws[8];
    int tx = threadIdx.x, ty = threadIdx.y;
    int b = blockIdx.z;
    int c0 = blockIdx.y * 32;
    int hw0 = blockIdx.x * 32;

    if (ty == 0) sidx[tx] = g_idx[b * HWS + hw0 + tx];
    __syncthreads();

    #pragma unroll
    for (int rr = ty; rr < 32; rr += 8)
        tile[rr][tx] = cb[sidx[rr] * EDIM + c0 + tx];   // tile[hw][c], coalesced over c
    __syncthreads();

    float ls = 0.f;
    #pragma unroll
    for (int cc = ty; cc < 32; cc += 8) {
        int o = b * CHW + (c0 + cc) * HWS + hw0 + tx;   // coalesced over tx
        float q = tile[tx][cc];
        float d = q - z[o];
        ls += d * d;
        zq_out[o] = q;
    }

    // block reduction (deterministic)
    #pragma unroll
    for (int off = 16; off; off >>= 1) ls += __shfl_xor_sync(0xffffffffu, ls, off);
    if (tx == 0) ws[ty] = ls;
    __syncthreads();
    if (ty == 0 && tx == 0) {
        float v = 0.f;
        #pragma unroll
        for (int i = 0; i < 8; ++i) v += ws[i];
        g_partials[(blockIdx.z * gridDim.y + blockIdx.y) * gridDim.x + blockIdx.x] = v;
    }
}

// ---------------------------------------------------------------------------
// Kernel 5: final deterministic reduction of loss partials + scalar outputs.
// ---------------------------------------------------------------------------
__global__ void __launch_bounds__(1024) reduce_kernel(float* __restrict__ dout, int n) {
    __shared__ float sm[1024];
    int t = threadIdx.x;
    float s = 0.f;
    for (int i = t; i < n; i += 1024) s += g_partials[i];
    sm[t] = s;
    __syncthreads();
    for (int st = 512; st; st >>= 1) {
        if (t < st) sm[t] += sm[t + st];
        __syncthreads();
    }
    if (t == 0) {
        dout[ZQ_ELEMS]     = sm[0] / (float)ZQ_ELEMS;  // codebook_loss (mean sq err)
        dout[ZQ_ELEMS + 1] = 0.0f;                     // cls_loss
    }
}

// ---------------------------------------------------------------------------
extern "C" void kernel_launch(void* const* d_in, const int* in_sizes, int n_in,
                              void* d_out, int out_size) {
    const float* z  = (const float*)d_in[0];   // (32,256,64,64)
    const float* cb = (const float*)d_in[1];   // (1024,256)
    float* out = (float*)d_out;

    (void)in_sizes; (void)n_in; (void)out_size;

    cbnorm_kernel<<<NE, 256>>>(cb);
    transpose_kernel<<<dim3(HWS / 32, CCH / 32, BB), dim3(32, 8)>>>(z);
    argmin_kernel<<<NROWS / 64, 256>>>(cb, out + ZQ_ELEMS + 2);
    gather_kernel<<<dim3(HWS / 32, CCH / 32, BB), dim3(32, 8)>>>(z, cb, out);
    reduce_kernel<<<1, 1024>>>(out, (HWS / 32) * (CCH / 32) * BB);
}

// round 4
// speedup vs baseline: 2.0242x; 2.0242x over previous
#include <cuda_runtime.h>
#include <cuda_bf16.h>
#include <cstdint>

typedef unsigned long long u64;
typedef unsigned int u32;

// Problem constants
#define BB   32
#define CCH  256
#define HH   64
#define WW   64
#define HWS  (HH * WW)            // 4096
#define NROWS (BB * HWS)          // 131072
#define EDIM 256
#define NE   1024
#define CHW  (CCH * HWS)          // 1048576
#define ZQ_ELEMS (BB * CHW)       // 8388608

// Output layout: [0,ZQ) z_q | [ZQ] loss | [ZQ+1] cls | [ZQ+2, +NROWS) indices f32

// ---------------- scratch ----------------
__device__ float           g_zt[NROWS * EDIM];    // exact fp32 z, transposed (N,256)
__device__ __nv_bfloat16   g_zh[NROWS * EDIM];    // bf16 hi
__device__ __nv_bfloat16   g_zl[NROWS * EDIM];    // bf16 lo
__device__ __nv_bfloat16   g_ch[NE * EDIM];
__device__ __nv_bfloat16   g_cl[NE * EDIM];
__device__ float           g_cbnorm[NE];
__device__ int             g_cand[NROWS * 4];
__device__ int             g_idx[NROWS];
__device__ float           g_partials[32768];

// ---------------- helpers ----------------
__device__ __forceinline__ u32 smem_u32(const void* p) {
    u32 a;
    asm("{ .reg .u64 t; cvta.to.shared.u64 t, %1; cvt.u32.u64 %0, t; }" : "=r"(a) : "l"(p));
    return a;
}
__device__ __forceinline__ void cp16(u32 dst, const void* src) {
    asm volatile("cp.async.cg.shared.global [%0], [%1], 16;" :: "r"(dst), "l"(src));
}
__device__ __forceinline__ void cp_commit() { asm volatile("cp.async.commit_group;" ::: "memory"); }
template <int N>
__device__ __forceinline__ void cp_wait() { asm volatile("cp.async.wait_group %0;" :: "n"(N) : "memory"); }

__device__ __forceinline__ void mma_bf16(float* c, const u32* a, u32 b0, u32 b1) {
    asm volatile(
        "mma.sync.aligned.m16n8k16.row.col.f32.bf16.bf16.f32 "
        "{%0,%1,%2,%3}, {%4,%5,%6,%7}, {%8,%9}, {%0,%1,%2,%3};"
        : "+f"(c[0]), "+f"(c[1]), "+f"(c[2]), "+f"(c[3])
        : "r"(a[0]), "r"(a[1]), "r"(a[2]), "r"(a[3]), "r"(b0), "r"(b1));
}

__device__ __forceinline__ u64 packsc(float s, int code) {
    u32 u = __float_as_uint(s);
    u = (u & 0x80000000u) ? ~u : (u | 0x80000000u);
    return ((u64)u << 32) | (u32)code;
}
__device__ __forceinline__ void ins4(u64* p, u64 x) {
    if (x < p[3]) {
        p[3] = x;
        u64 t;
        if (p[3] < p[2]) { t = p[2]; p[2] = p[3]; p[3] = t; }
        if (p[2] < p[1]) { t = p[1]; p[1] = p[2]; p[2] = t; }
        if (p[1] < p[0]) { t = p[0]; p[0] = p[1]; p[1] = t; }
    }
}

// ---------------------------------------------------------------------------
// Kernel 1: codebook prep — bf16 hi/lo split + norms. One block per code.
// ---------------------------------------------------------------------------
__global__ void __launch_bounds__(256) prep_cb_kernel(const float* __restrict__ cb) {
    int j = blockIdx.x;
    int t = threadIdx.x;
    float v = cb[j * EDIM + t];
    __nv_bfloat16 hi = __float2bfloat16(v);
    float hif = __bfloat162float(hi);
    g_ch[j * EDIM + t] = hi;
    g_cl[j * EDIM + t] = __float2bfloat16(v - hif);
    float s = v * v;
    #pragma unroll
    for (int off = 16; off; off >>= 1) s += __shfl_xor_sync(0xffffffffu, s, off);
    __shared__ float ws[8];
    if ((t & 31) == 0) ws[t >> 5] = s;
    __syncthreads();
    if (t == 0) {
        float tot = 0.f;
        #pragma unroll
        for (int i = 0; i < 8; ++i) tot += ws[i];
        g_cbnorm[j] = tot;
    }
}

// ---------------------------------------------------------------------------
// Kernel 2: transpose z -> (N,256): fp32 exact + bf16 hi/lo split.
// ---------------------------------------------------------------------------
__global__ void __launch_bounds__(256) prep_z_kernel(const float* __restrict__ z) {
    __shared__ float t[32][33];
    int tx = threadIdx.x, ty = threadIdx.y;
    int b = blockIdx.z;
    int c0 = blockIdx.y * 32;
    int hw0 = blockIdx.x * 32;
    #pragma unroll
    for (int cc = ty; cc < 32; cc += 8)
        t[cc][tx] = z[b * CHW + (c0 + cc) * HWS + hw0 + tx];
    __syncthreads();
    #pragma unroll
    for (int rr = ty; rr < 32; rr += 8) {
        float v = t[tx][rr];
        size_t o = (size_t)(b * HWS + hw0 + rr) * EDIM + c0 + tx;
        g_zt[o] = v;
        __nv_bfloat16 hi = __float2bfloat16(v);
        g_zh[o] = hi;
        g_zl[o] = __float2bfloat16(v - __bfloat162float(hi));
    }
}

// ---------------------------------------------------------------------------
// Kernel 3: bf16x3 mma.sync distance GEMM + fused top-4 argmin.
// 128 rows/CTA vs all 1024 codes. A resident in smem; B double-buffered.
// ---------------------------------------------------------------------------
#define A_STRIDE 264               // 256 + 8 bf16 pad (16B): conflict-free
#define B_STRIDE 40                // 32 + 8 bf16 pad
#define OFF_AH 0
#define OFF_AL (128 * A_STRIDE * 2)                      // 67584
#define OFF_B  (2 * 128 * A_STRIDE * 2)                  // 135168
#define B_ARR  (128 * B_STRIDE * 2)                      // 10240 per array
#define B_BUF  (2 * B_ARR)                               // 20480 per buffer
#define OFF_CBN (OFF_B + 2 * B_BUF)                      // 176128
#define OFF_TOP (OFF_CBN + NE * 4)                       // 180224
#define SMEM_DYN (OFF_TOP + 128 * 2 * 4 * 8)             // 188416

__global__ void __launch_bounds__(256, 1) argmin_mma_kernel() {
    extern __shared__ char smem[];
    u32 sb = smem_u32(smem);
    const __nv_bfloat16* sAh = (const __nv_bfloat16*)(smem + OFF_AH);
    const __nv_bfloat16* sAl = (const __nv_bfloat16*)(smem + OFF_AL);
    float* cbn_s = (float*)(smem + OFF_CBN);
    u64* topb = (u64*)(smem + OFF_TOP);

    int tid = threadIdx.x;
    int warp = tid >> 5;
    int lane = tid & 31;
    int g = lane >> 2;       // groupID
    int tig2 = (lane & 3) * 2;
    int mw = warp >> 1;      // M warp (0..3): rows mw*32..+31
    int nw = warp & 1;       // N warp (0..1): cols nw*64..+63
    int n0 = blockIdx.x * 128;

    // cbn -> smem
    for (int i = tid; i < NE; i += 256) cbn_s[i] = g_cbnorm[i];

    // issue first B tile (nt=0, kc=0) into buf 0
    {
        #pragma unroll
        for (int u = 0; u < 2; ++u) {
            int e = tid + u * 256;
            int r = e >> 2, c8 = e & 3;
            u32 db = sb + OFF_B + 0 * B_BUF + r * (B_STRIDE * 2) + c8 * 16;
            cp16(db,         &g_ch[(size_t)r * EDIM + c8 * 8]);
            cp16(db + B_ARR, &g_cl[(size_t)r * EDIM + c8 * 8]);
        }
        cp_commit();
    }

    // load A (128 rows x 256 k, hi+lo) into smem — plain ld/st
    #pragma unroll
    for (int u = 0; u < 16; ++u) {
        int e = tid + u * 256;
        int r = e >> 5, c8 = e & 31;
        uint4 vh = *(const uint4*)&g_zh[(size_t)(n0 + r) * EDIM + c8 * 8];
        uint4 vl = *(const uint4*)&g_zl[(size_t)(n0 + r) * EDIM + c8 * 8];
        *(uint4*)((char*)smem + OFF_AH + r * (A_STRIDE * 2) + c8 * 16) = vh;
        *(uint4*)((char*)smem + OFF_AL + r * (A_STRIDE * 2) + c8 * 16) = vl;
    }

    float acc[2][8][4] = {};
    u64 top[4][4];
    #pragma unroll
    for (int s = 0; s < 4; ++s)
        #pragma unroll
        for (int j = 0; j < 4; ++j) top[s][j] = 0xFFFFFFFFFFFFFFFFULL;

    #pragma unroll 1
    for (int t = 0; t < 64; ++t) {
        // prefetch next B tile
        if (t < 63) {
            int tn = t + 1;
            int nt_n = tn >> 3, kc_n = tn & 7, buf_n = tn & 1;
            #pragma unroll
            for (int u = 0; u < 2; ++u) {
                int e = tid + u * 256;
                int r = e >> 2, c8 = e & 3;
                u32 db = sb + OFF_B + buf_n * B_BUF + r * (B_STRIDE * 2) + c8 * 16;
                size_t gs = (size_t)(nt_n * 128 + r) * EDIM + kc_n * 32 + c8 * 8;
                cp16(db,         &g_ch[gs]);
                cp16(db + B_ARR, &g_cl[gs]);
            }
            cp_commit();
            cp_wait<1>();
        } else {
            cp_wait<0>();
        }
        __syncthreads();

        int kc = t & 7, buf = t & 1;
        const __nv_bfloat16* sBh = (const __nv_bfloat16*)(smem + OFF_B + buf * B_BUF);
        const __nv_bfloat16* sBl = (const __nv_bfloat16*)(smem + OFF_B + buf * B_BUF + B_ARR);

        #pragma unroll
        for (int ks = 0; ks < 32; ks += 16) {
            int kk = kc * 32 + ks + tig2;
            u32 ah[2][4], al[2][4];
            #pragma unroll
            for (int mf = 0; mf < 2; ++mf) {
                int r0 = mw * 32 + mf * 16 + g;
                ah[mf][0] = *(const u32*)&sAh[r0 * A_STRIDE + kk];
                ah[mf][1] = *(const u32*)&sAh[(r0 + 8) * A_STRIDE + kk];
                ah[mf][2] = *(const u32*)&sAh[r0 * A_STRIDE + kk + 8];
                ah[mf][3] = *(const u32*)&sAh[(r0 + 8) * A_STRIDE + kk + 8];
                al[mf][0] = *(const u32*)&sAl[r0 * A_STRIDE + kk];
                al[mf][1] = *(const u32*)&sAl[(r0 + 8) * A_STRIDE + kk];
                al[mf][2] = *(const u32*)&sAl[r0 * A_STRIDE + kk + 8];
                al[mf][3] = *(const u32*)&sAl[(r0 + 8) * A_STRIDE + kk + 8];
            }
            #pragma unroll
            for (int nf = 0; nf < 8; ++nf) {
                int n = nw * 64 + nf * 8 + g;
                int kb = ks + tig2;
                u32 bh0 = *(const u32*)&sBh[n * B_STRIDE + kb];
                u32 bh1 = *(const u32*)&sBh[n * B_STRIDE + kb + 8];
                u32 bl0 = *(const u32*)&sBl[n * B_STRIDE + kb];
                u32 bl1 = *(const u32*)&sBl[n * B_STRIDE + kb + 8];
                #pragma unroll
                for (int mf = 0; mf < 2; ++mf) {
                    mma_bf16(acc[mf][nf], ah[mf], bh0, bh1);  // hi*hi
                    mma_bf16(acc[mf][nf], ah[mf], bl0, bl1);  // hi*lo
                    mma_bf16(acc[mf][nf], al[mf], bh0, bh1);  // lo*hi
                }
            }
        }

        // end of this ntile's K: fused score + top-4 update
        if (kc == 7) {
            int jbase = (t >> 3) * 128;
            #pragma unroll
            for (int mf = 0; mf < 2; ++mf)
                #pragma unroll
                for (int nf = 0; nf < 8; ++nf) {
                    int code0 = jbase + nw * 64 + nf * 8 + tig2;
                    float cb0 = cbn_s[code0], cb1 = cbn_s[code0 + 1];
                    float s0 = cb0 - 2.0f * acc[mf][nf][0];
                    float s1 = cb1 - 2.0f * acc[mf][nf][1];
                    float s2 = cb0 - 2.0f * acc[mf][nf][2];
                    float s3 = cb1 - 2.0f * acc[mf][nf][3];
                    ins4(top[mf * 2 + 0], packsc(s0, code0));
                    ins4(top[mf * 2 + 0], packsc(s1, code0 + 1));
                    ins4(top[mf * 2 + 1], packsc(s2, code0));
                    ins4(top[mf * 2 + 1], packsc(s3, code0 + 1));
                    acc[mf][nf][0] = acc[mf][nf][1] = acc[mf][nf][2] = acc[mf][nf][3] = 0.f;
                }
        }
        __syncthreads();
    }

    // quad merge (lanes tig 0..3 hold different cols of the same rows)
    #pragma unroll
    for (int off = 1; off <= 2; off <<= 1) {
        #pragma unroll
        for (int s = 0; s < 4; ++s) {
            u64 q0 = __shfl_xor_sync(0xffffffffu, top[s][0], off);
            u64 q1 = __shfl_xor_sync(0xffffffffu, top[s][1], off);
            u64 q2 = __shfl_xor_sync(0xffffffffu, top[s][2], off);
            u64 q3 = __shfl_xor_sync(0xffffffffu, top[s][3], off);
            ins4(top[s], q0); ins4(top[s], q1); ins4(top[s], q2); ins4(top[s], q3);
        }
    }
    if ((lane & 3) == 0) {
        #pragma unroll
        for (int s = 0; s < 4; ++s) {
            int mf = s >> 1, h = s & 1;
            int r = mw * 32 + mf * 16 + h * 8 + g;
            #pragma unroll
            for (int j = 0; j < 4; ++j) topb[(r * 2 + nw) * 4 + j] = top[s][j];
        }
    }
    __syncthreads();
    if (tid < 128) {
        u64 p[4];
        #pragma unroll
        for (int j = 0; j < 4; ++j) p[j] = topb[(tid * 2 + 0) * 4 + j];
        #pragma unroll
        for (int j = 0; j < 4; ++j) ins4(p, topb[(tid * 2 + 1) * 4 + j]);
        #pragma unroll
        for (int j = 0; j < 4; ++j)
            g_cand[(size_t)(n0 + tid) * 4 + j] = (int)(p[j] & 0xFFFFFFFFULL);
    }
}

// ---------------------------------------------------------------------------
// Kernel 4: exact fp32 rescore of 4 candidates per row. One warp per row.
// ---------------------------------------------------------------------------
__global__ void __launch_bounds__(256) fixup_kernel(const float* __restrict__ cb,
                                                    float* __restrict__ out_idx_f) {
    int warp = threadIdx.x >> 5;
    int lid = threadIdx.x & 31;
    int row = blockIdx.x * 8 + warp;
    int c[4];
    #pragma unroll
    for (int j = 0; j < 4; ++j) c[j] = g_cand[(size_t)row * 4 + j];
    float d[4] = {};
    #pragma unroll
    for (int m = 0; m < 8; ++m) {
        int k = m * 32 + lid;
        float zv = g_zt[(size_t)row * EDIM + k];
        #pragma unroll
        for (int j = 0; j < 4; ++j) d[j] += zv * cb[c[j] * EDIM + k];
    }
    #pragma unroll
    for (int off = 16; off; off >>= 1) {
        #pragma unroll
        for (int j = 0; j < 4; ++j) d[j] += __shfl_xor_sync(0xffffffffu, d[j], off);
    }
    if (lid == 0) {
        float bs = __int_as_float(0x7f800000);
        int bi = 0x7fffffff;
        #pragma unroll
        for (int j = 0; j < 4; ++j) {
            float s = g_cbnorm[c[j]] - 2.0f * d[j];
            if (s < bs || (s == bs && c[j] < bi)) { bs = s; bi = c[j]; }
        }
        g_idx[row] = bi;
        out_idx_f[row] = (float)bi;
    }
}

// ---------------------------------------------------------------------------
// Kernel 5: gather z_q + squared-error partials.
// ---------------------------------------------------------------------------
__global__ void __launch_bounds__(256) gather_kernel(const float* __restrict__ z,
                                                     const float* __restrict__ cb,
                                                     float* __restrict__ zq_out) {
    __shared__ float tile[32][33];
    __shared__ int sidx[32];
    __shared__ float ws[8];
    int tx = threadIdx.x, ty = threadIdx.y;
    int b = blockIdx.z;
    int c0 = blockIdx.y * 32;
    int hw0 = blockIdx.x * 32;

    if (ty == 0) sidx[tx] = g_idx[b * HWS + hw0 + tx];
    __syncthreads();
    #pragma unroll
    for (int rr = ty; rr < 32; rr += 8)
        tile[rr][tx] = cb[sidx[rr] * EDIM + c0 + tx];
    __syncthreads();

    float ls = 0.f;
    #pragma unroll
    for (int cc = ty; cc < 32; cc += 8) {
        int o = b * CHW + (c0 + cc) * HWS + hw0 + tx;
        float q = tile[tx][cc];
        float d = q - z[o];
        ls += d * d;
        zq_out[o] = q;
    }
    #pragma unroll
    for (int off = 16; off; off >>= 1) ls += __shfl_xor_sync(0xffffffffu, ls, off);
    if (tx == 0) ws[ty] = ls;
    __syncthreads();
    if (ty == 0 && tx == 0) {
        float v = 0.f;
        #pragma unroll
        for (int i = 0; i < 8; ++i) v += ws[i];
        g_partials[(blockIdx.z * gridDim.y + blockIdx.y) * gridDim.x + blockIdx.x] = v;
    }
}

// ---------------------------------------------------------------------------
// Kernel 6: deterministic final loss reduction.
// ---------------------------------------------------------------------------
__global__ void __launch_bounds__(1024) reduce_kernel(float* __restrict__ dout, int n) {
    __shared__ float sm[1024];
    int t = threadIdx.x;
    float s = 0.f;
    for (int i = t; i < n; i += 1024) s += g_partials[i];
    sm[t] = s;
    __syncthreads();
    for (int st = 512; st; st >>= 1) {
        if (t < st) sm[t] += sm[t + st];
        __syncthreads();
    }
    if (t == 0) {
        dout[ZQ_ELEMS]     = sm[0] / (float)ZQ_ELEMS;
        dout[ZQ_ELEMS + 1] = 0.0f;
    }
}

// ---------------------------------------------------------------------------
extern "C" void kernel_launch(void* const* d_in, const int* in_sizes, int n_in,
                              void* d_out, int out_size) {
    const float* z  = (const float*)d_in[0];
    const float* cb = (const float*)d_in[1];
    float* out = (float*)d_out;
    (void)in_sizes; (void)n_in; (void)out_size;

    cudaFuncSetAttribute(argmin_mma_kernel, cudaFuncAttributeMaxDynamicSharedMemorySize, SMEM_DYN);

    prep_cb_kernel<<<NE, 256>>>(cb);
    prep_z_kernel<<<dim3(HWS / 32, CCH / 32, BB), dim3(32, 8)>>>(z);
    argmin_mma_kernel<<<NROWS / 128, 256, SMEM_DYN>>>();
    fixup_kernel<<<NROWS / 8, 256>>>(cb, out + ZQ_ELEMS + 2);
    gather_kernel<<<dim3(HWS / 32, CCH / 32, BB), dim3(32, 8)>>>(z, cb, out);
    reduce_kernel<<<1, 1024>>>(out, (HWS / 32) * (CCH / 32) * BB);
}